// round 4
// baseline (speedup 1.0000x reference)
#include <cuda_runtime.h>
#include <cstdint>

// ===========================================================================
// MaskedCouplingRQS — Round 3: mma.sync (HMMA tf32) GEMMs + fused RQS spline
//   (tcgen05 is rejected by this harness's compute_103 PTX target)
// ===========================================================================

#define THREADS 256

// ---- shared memory layout (float indices) ----
#define SA   132                     // A tile stride (4 mod 32 -> conflict-free)
#define SW   68                      // weight buffer stride (4 mod 32)
#define SP   104                     // P buffer stride
#define SX   36                      // x_trans buffer stride (16B-aligned rows)
#define A_F    0                     // 128*132          = 16896
#define WB0_F  16896                 // 128*68           =  8704
#define WB1_F  25600                 //                  =  8704
#define P_F    34304                 // 128*104          = 13312
#define XTR_F  47616                 // 128*36           =  4608
#define B1_F   52224
#define B2_F   52352
#define B3_F   52480
#define B4_F   52608                 // 800
#define SMEM_F 53408
#define SMEM_BYTES (SMEM_F * 4)      // 213,632 B

// --------------------------- small helpers ---------------------------------
__device__ __forceinline__ void cp16(float* dst, const float* src) {
    uint32_t s = (uint32_t)__cvta_generic_to_shared(dst);
    asm volatile("cp.async.cg.shared.global [%0], [%1], 16;" :: "r"(s), "l"(src));
}
__device__ __forceinline__ void cp_commit() { asm volatile("cp.async.commit_group;"); }
template<int N>
__device__ __forceinline__ void cp_wait() {
    asm volatile("cp.async.wait_group %0;" :: "n"(N) : "memory");
}
__device__ __forceinline__ uint32_t tf32_rna(float f) {
    uint32_t u;
    asm("cvt.rna.tf32.f32 %0, %1;" : "=r"(u) : "f"(f));
    return u;
}
__device__ __forceinline__ void mma8(float* c, uint32_t a0, uint32_t a1,
                                     uint32_t a2, uint32_t a3,
                                     uint32_t b0, uint32_t b1) {
    asm volatile(
        "mma.sync.aligned.m16n8k8.row.col.f32.tf32.tf32.f32 "
        "{%0,%1,%2,%3}, {%4,%5,%6,%7}, {%8,%9}, {%0,%1,%2,%3};"
        : "+f"(c[0]), "+f"(c[1]), "+f"(c[2]), "+f"(c[3])
        : "r"(a0), "r"(a1), "r"(a2), "r"(a3), "r"(b0), "r"(b1));
}
__device__ __forceinline__ float softplus_f(float v) {
    return fmaxf(v, 0.f) + __logf(1.f + __expf(-fabsf(v)));
}

// MMA over a K-slab: A (pre-offset to warp rows + k offset, stride SA),
// W in buf (stride SW, rows = output neurons, cols = local k).
template<int NT, int KT>
__device__ __forceinline__ void mma_tiles(const float* As, const float* Ws, float* C) {
    const int lane = threadIdx.x & 31;
    const int g = lane >> 2, m = lane & 3;
    #pragma unroll
    for (int kt = 0; kt < KT; kt++) {
        const int k = kt * 8 + m;
        uint32_t a0 = __float_as_uint(As[g * SA + k]);
        uint32_t a1 = __float_as_uint(As[(g + 8) * SA + k]);
        uint32_t a2 = __float_as_uint(As[g * SA + k + 4]);
        uint32_t a3 = __float_as_uint(As[(g + 8) * SA + k + 4]);
        #pragma unroll
        for (int nt = 0; nt < NT; nt++) {
            uint32_t b0 = __float_as_uint(Ws[(nt * 8 + g) * SW + k]);
            uint32_t b1 = __float_as_uint(Ws[(nt * 8 + g) * SW + k + 4]);
            mma8(C + nt * 4, a0, a1, a2, a3, b0, b1);
        }
    }
}

// relu(C + bias) -> A tile (own warp rows only), stored pre-rounded to tf32.
__device__ __forceinline__ void relu_store(const float* C, const float* bs,
                                           float* A, int R0) {
    const int lane = threadIdx.x & 31;
    const int g = lane >> 2, m = lane & 3;
    #pragma unroll
    for (int nt = 0; nt < 16; nt++) {
        const int c0 = nt * 8 + 2 * m, c1 = c0 + 1;
        const float b0 = bs[c0], b1 = bs[c1];
        A[(R0 + g) * SA + c0]     = __uint_as_float(tf32_rna(fmaxf(C[nt*4+0] + b0, 0.f)));
        A[(R0 + g) * SA + c1]     = __uint_as_float(tf32_rna(fmaxf(C[nt*4+1] + b1, 0.f)));
        A[(R0 + g + 8) * SA + c0] = __uint_as_float(tf32_rna(fmaxf(C[nt*4+2] + b0, 0.f)));
        A[(R0 + g + 8) * SA + c1] = __uint_as_float(tf32_rna(fmaxf(C[nt*4+3] + b1, 0.f)));
    }
}

__device__ __forceinline__ void p_store(const float* C, float* P, int R0) {
    const int lane = threadIdx.x & 31;
    const int g = lane >> 2, m = lane & 3;
    #pragma unroll
    for (int nt = 0; nt < 13; nt++) {
        const int c0 = nt * 8 + 2 * m, c1 = c0 + 1;
        P[(R0 + g) * SP + c0]     = C[nt*4+0];
        P[(R0 + g) * SP + c1]     = C[nt*4+1];
        P[(R0 + g + 8) * SP + c0] = C[nt*4+2];
        P[(R0 + g + 8) * SP + c1] = C[nt*4+3];
    }
}

// in-place tf32 rounding of a landed weight buffer (128*SW words)
__device__ __forceinline__ void conv_buf(float* buf) {
    for (int i = threadIdx.x; i < 128 * SW / 4; i += THREADS) {
        float4 v = *(float4*)(buf + i * 4);
        v.x = __uint_as_float(tf32_rna(v.x));
        v.y = __uint_as_float(tf32_rna(v.y));
        v.z = __uint_as_float(tf32_rna(v.z));
        v.w = __uint_as_float(tf32_rna(v.w));
        *(float4*)(buf + i * 4) = v;
    }
}

// stage one K-half of a weight matrix: nrows x 64 from src (+ofs), 16B chunks
__device__ __forceinline__ void stage_w(float* dst, const float* src,
                                        int nrows, int stride, int ofs) {
    for (int i = threadIdx.x; i < nrows * 16; i += THREADS) {
        int row = i >> 4, j = i & 15;
        cp16(dst + row * SW + j * 4, src + row * stride + ofs + j * 4);
    }
}

// ---------------------------------------------------------------------------
__global__ __launch_bounds__(THREADS, 1)
void rqs_mma_kernel(const float* __restrict__ x,
                    const float* __restrict__ W1, const float* __restrict__ b1,
                    const float* __restrict__ W2, const float* __restrict__ b2,
                    const float* __restrict__ W3, const float* __restrict__ b3,
                    const float* __restrict__ W4, const float* __restrict__ b4,
                    float* __restrict__ out, int B)
{
    extern __shared__ float sm[];
    float* A   = sm + A_F;
    float* WBa = sm + WB0_F;
    float* WBb = sm + WB1_F;
    float* P   = sm + P_F;
    float* XTR = sm + XTR_F;
    float* B1S = sm + B1_F;
    float* B2S = sm + B2_F;
    float* B3S = sm + B3_F;
    float* B4S = sm + B4_F;

    const int tid = threadIdx.x;
    const int w   = tid >> 5;
    const int R0  = w * 16;
    const long row0 = (long)blockIdx.x * 128;

    // ---- G0: x -> A(cols 0..31) + XTR, biases, W1 -> WBa ----
    for (int i = tid; i < 1024; i += THREADS) {        // x masked
        int row = i >> 3, j = i & 7;
        if (row0 + row < B)
            cp16(A + row * SA + j * 4, x + (row0 + row) * 64 + j * 4);
    }
    for (int i = tid; i < 1024; i += THREADS) {        // x trans
        int row = i >> 3, j = i & 7;
        if (row0 + row < B)
            cp16(XTR + row * SX + j * 4, x + (row0 + row) * 64 + 32 + j * 4);
    }
    for (int i = tid; i < 32; i += THREADS) {
        cp16(B1S + i * 4, b1 + i * 4);
        cp16(B2S + i * 4, b2 + i * 4);
        cp16(B3S + i * 4, b3 + i * 4);
    }
    for (int i = tid; i < 200; i += THREADS) cp16(B4S + i * 4, b4 + i * 4);
    for (int i = tid; i < 1024; i += THREADS) {        // W1 (128x32)
        int row = i >> 3, j = i & 7;
        cp16(WBa + row * SW + j * 4, W1 + row * 32 + j * 4);
    }
    cp_commit();                                       // G0
    stage_w(WBb, W2, 128, 128, 0);  cp_commit();       // G1: W2 k-half 0

    cp_wait<1>(); __syncthreads();
    conv_buf(WBa);
    // round x_masked to tf32 in place
    for (int i = tid; i < 1024; i += THREADS) {
        int row = i >> 3, c4 = i & 7;
        float4 v = *(float4*)(A + row * SA + c4 * 4);
        v.x = __uint_as_float(tf32_rna(v.x));
        v.y = __uint_as_float(tf32_rna(v.y));
        v.z = __uint_as_float(tf32_rna(v.z));
        v.w = __uint_as_float(tf32_rna(v.w));
        *(float4*)(A + row * SA + c4 * 4) = v;
    }
    __syncthreads();

    float C64[64];

    // ---- Layer 1 (K=32) ----
    #pragma unroll
    for (int i = 0; i < 64; i++) C64[i] = 0.f;
    mma_tiles<16, 4>(A + R0 * SA, WBa, C64);
    relu_store(C64, B1S, A, R0);                        // h1
    __syncthreads();
    stage_w(WBa, W2, 128, 128, 64); cp_commit();        // G2: W2 k-half 1

    // ---- Layer 2 ----
    cp_wait<1>(); __syncthreads(); conv_buf(WBb); __syncthreads();
    #pragma unroll
    for (int i = 0; i < 64; i++) C64[i] = 0.f;
    mma_tiles<16, 8>(A + R0 * SA, WBb, C64);
    __syncthreads();
    stage_w(WBb, W3, 128, 128, 0);  cp_commit();        // G3: W3 k-half 0
    cp_wait<1>(); __syncthreads(); conv_buf(WBa); __syncthreads();
    mma_tiles<16, 8>(A + R0 * SA + 64, WBa, C64);
    relu_store(C64, B2S, A, R0);                        // h2
    __syncthreads();
    stage_w(WBa, W3, 128, 128, 64); cp_commit();        // G4: W3 k-half 1

    // ---- Layer 3 ----
    cp_wait<1>(); __syncthreads(); conv_buf(WBb); __syncthreads();
    #pragma unroll
    for (int i = 0; i < 64; i++) C64[i] = 0.f;
    mma_tiles<16, 8>(A + R0 * SA, WBb, C64);
    __syncthreads();
    stage_w(WBb, W4, 100, 128, 0);  cp_commit();        // G5: W4 c0 k-half 0
    cp_wait<1>(); __syncthreads(); conv_buf(WBa); __syncthreads();
    mma_tiles<16, 8>(A + R0 * SA + 64, WBa, C64);
    relu_store(C64, B3S, A, R0);                        // h3
    __syncthreads();

    // ---- Layer 4: 8 chunks of 4 spline dims (100 cols, padded to 104) ----
    const float MINB = 1e-4f;
    const float FREE = 10.f - 8.f * 1e-4f;
    const int trow = tid >> 1;
    float ldsum = 0.f;

    for (int c = 0; c < 8; c++) {
        stage_w(WBa, W4 + (size_t)c * 100 * 128, 100, 128, 64); cp_commit(); // c h1
        cp_wait<1>(); __syncthreads(); conv_buf(WBb); __syncthreads();

        float C52[52];
        #pragma unroll
        for (int i = 0; i < 52; i++) C52[i] = 0.f;
        mma_tiles<13, 8>(A + R0 * SA, WBb, C52);
        __syncthreads();
        if (c < 7) { stage_w(WBb, W4 + (size_t)(c + 1) * 100 * 128, 100, 128, 0); cp_commit(); }
        if (c < 7) { cp_wait<1>(); } else { cp_wait<0>(); }
        __syncthreads(); conv_buf(WBa); __syncthreads();
        mma_tiles<13, 8>(A + R0 * SA + 64, WBa, C52);
        p_store(C52, P, R0);
        __syncthreads();

        // ---------------- spline epilogue: 2 (row,dim) tasks/thread --------
        #pragma unroll
        for (int j = 0; j < 2; j++) {
            const int q = 2 * (tid & 1) + j;          // dim within chunk 0..3
            const int t = c * 4 + q;                  // global transform dim

            float acc[25];
            #pragma unroll
            for (int p = 0; p < 25; p++)
                acc[p] = P[trow * SP + q * 25 + p] + B4S[c * 100 + q * 25 + p];

            float m = acc[0];
            #pragma unroll
            for (int i = 1; i < 8; i++) m = fmaxf(m, acc[i]);
            float wdt[8]; float Sw = 0.f;
            #pragma unroll
            for (int i = 0; i < 8; i++) { wdt[i] = __expf(acc[i] - m); Sw += wdt[i]; }
            float mh = acc[8];
            #pragma unroll
            for (int i = 9; i < 16; i++) mh = fmaxf(mh, acc[i]);
            float hgt[8]; float Sh = 0.f;
            #pragma unroll
            for (int i = 0; i < 8; i++) { hgt[i] = __expf(acc[8 + i] - mh); Sh += hgt[i]; }
            const float fw = FREE / Sw, fh = FREE / Sh;
            #pragma unroll
            for (int i = 0; i < 8; i++) {
                wdt[i] = MINB + wdt[i] * fw;
                hgt[i] = MINB + hgt[i] * fh;
            }

            const float xt = XTR[trow * SX + t];
            const float xc = fminf(fmaxf(xt, -5.f), 5.f);
            const bool inside = (xt >= -5.f) && (xt <= 5.f);

            int idx = 0; float cum = -5.f, xk = -5.f, wk = wdt[0];
            #pragma unroll
            for (int i = 0; i < 7; i++) {
                cum += wdt[i];
                if (xc >= cum) { idx = i + 1; xk = cum; wk = wdt[i + 1]; }
            }
            float cumh = -5.f, yk = -5.f, hk = hgt[0];
            #pragma unroll
            for (int i = 0; i < 7; i++) {
                cumh += hgt[i];
                if (idx > i) { yk = cumh; hk = hgt[i + 1]; }
            }
            float sA = acc[16], sB = acc[17];
            #pragma unroll
            for (int i = 1; i < 8; i++)
                if (idx >= i) { sA = acc[16 + i]; sB = acc[17 + i]; }
            const float dk  = 1e-4f + softplus_f(sA);
            const float dk1 = 1e-4f + softplus_f(sB);

            const float rwk  = 1.f / wk;
            const float xi   = (xc - xk) * rwk;
            const float om   = 1.f - xi;
            const float sk   = hk * rwk;
            const float xiom = xi * om;
            const float den  = sk + (dk1 + dk - 2.f * sk) * xiom;
            const float rden = 1.f / den;
            const float num  = sk * xi * xi + dk * xiom;
            const float y_in = yk + hk * num * rden;
            const float num2 = dk1 * xi * xi + 2.f * sk * xiom + dk * om * om;
            const float ld_in = __logf(sk * sk * num2 * rden * rden);

            XTR[trow * SX + t] = inside ? y_in : xt;
            ldsum += inside ? ld_in : 0.f;
        }
        // (loop-top staging into WBa is safe: all warps passed the P-store sync)
    }

    // ---- logdet: pair-reduce (tid, tid^1 share a row) ----
    ldsum += __shfl_xor_sync(0xFFFFFFFFu, ldsum, 1);
    if ((tid & 1) == 0 && row0 + trow < B)
        out[(size_t)B * 64 + row0 + trow] = ldsum;

    __syncthreads();   // XTR y-writes visible to flush

    // ---- flush y: cols 0..31 = x_masked (re-read, L2-hot), 32..63 = XTR ----
    for (int i = tid; i < 2048; i += THREADS) {
        int rr = i >> 4, c4 = i & 15;
        if (row0 + rr >= B) continue;
        float4 v;
        if (c4 < 8) v = *(const float4*)(x + (row0 + rr) * 64 + c4 * 4);
        else        v = *(const float4*)(XTR + rr * SX + (c4 - 8) * 4);
        *(float4*)(out + (row0 + rr) * 64 + c4 * 4) = v;
    }
}

// ---------------------------------------------------------------------------
extern "C" void kernel_launch(void* const* d_in, const int* in_sizes, int n_in,
                              void* d_out, int out_size)
{
    const float* x  = (const float*)d_in[0];
    const float* W1 = (const float*)d_in[1];
    const float* b1 = (const float*)d_in[2];
    const float* W2 = (const float*)d_in[3];
    const float* b2 = (const float*)d_in[4];
    const float* W3 = (const float*)d_in[5];
    const float* b3 = (const float*)d_in[6];
    const float* W4 = (const float*)d_in[7];
    const float* b4 = (const float*)d_in[8];
    float* out = (float*)d_out;

    const int B = in_sizes[0] / 64;

    cudaFuncSetAttribute(rqs_mma_kernel,
                         cudaFuncAttributeMaxDynamicSharedMemorySize, SMEM_BYTES);

    const int grid = (B + 127) / 128;
    rqs_mma_kernel<<<grid, THREADS, SMEM_BYTES>>>(x, W1, b1, W2, b2, W3, b3, W4, b4, out, B);
}

// round 6
// speedup vs baseline: 1.6833x; 1.6833x over previous
#include <cuda_runtime.h>
#include <cstdint>

// ===========================================================================
// MaskedCouplingRQS — Round 6: R5 design with the B-operand pack permutation
// fixed (prep wrote identity layout; mma reads the transpose within each
// 16-col K-group: position q=4m+j must hold k=m+4j).
// ===========================================================================

#define THREADS 256

// ---- shared memory layout (float indices) ----
#define SA   136                     // A stride: LDS.64 conflict-free
#define SW   80                      // W stride: LDS.128 conflict-free
#define SP   104
#define SX   36
#define A_F    0                     // 128*136 = 17408
#define WB0_F  17408                 // 128*80  = 10240
#define WB1_F  27648
#define P_F    37888                 // 128*104 = 13312
#define XTR_F  51200                 // 128*36  =  4608
#define B1_F   55808
#define B2_F   55936
#define B3_F   56064
#define B4_F   56192                 // 800 -> ends 56992
#define SMEM_BYTES (56992 * 4)       // 227,968 B

// packed weight buffer (tf32-rounded, interleaved)
#define WPK_W1   0                   // [128][32]
#define WPK_W2   4096                // 2 halves x [128][64]
#define WPK_W3   20480
#define WPK_W4   36864               // 16 units x [100][64]
#define WPK_TOT  139264
__device__ float g_wpk[WPK_TOT];

// --------------------------- helpers ---------------------------------------
__device__ __forceinline__ void cp16(float* dst, const float* src) {
    uint32_t s = (uint32_t)__cvta_generic_to_shared(dst);
    asm volatile("cp.async.cg.shared.global [%0], [%1], 16;" :: "r"(s), "l"(src));
}
__device__ __forceinline__ void cp_commit() { asm volatile("cp.async.commit_group;"); }
template<int N>
__device__ __forceinline__ void cp_wait() {
    asm volatile("cp.async.wait_group %0;" :: "n"(N) : "memory");
}
__device__ __forceinline__ uint32_t tf32_rna(float f) {
    uint32_t u;
    asm("cvt.rna.tf32.f32 %0, %1;" : "=r"(u) : "f"(f));
    return u;
}
#define F2U __float_as_uint
__device__ __forceinline__ void mma8(float* c, uint32_t a0, uint32_t a1,
                                     uint32_t a2, uint32_t a3,
                                     uint32_t b0, uint32_t b1) {
    asm volatile(
        "mma.sync.aligned.m16n8k8.row.col.f32.tf32.tf32.f32 "
        "{%0,%1,%2,%3}, {%4,%5,%6,%7}, {%8,%9}, {%0,%1,%2,%3};"
        : "+f"(c[0]), "+f"(c[1]), "+f"(c[2]), "+f"(c[3])
        : "r"(a0), "r"(a1), "r"(a2), "r"(a3), "r"(b0), "r"(b1));
}
__device__ __forceinline__ float softplus_f(float v) {
    return fmaxf(v, 0.f) + __logf(1.f + __expf(-fabsf(v)));
}
// interleaved A position for logical column c: pairs (k, k+4) adjacent
__device__ __forceinline__ int apos(int c) {
    return ((c >> 3) << 3) + ((c & 3) << 1) + ((c & 7) >> 2);
}

// ---------------------------------------------------------------------------
// prep: reorder + tf32-round all weights into g_wpk
//   Within each 16-col K-group of a 64-col half, packed position q (=4*mq+j,
//   mq=q>>2, j=q&3) holds logical k = kt2*16 + mq + 4*j.
//   (FIX vs R5: was k = kt2*16 + (q&3) + 4*(q>>2), the identity.)
// ---------------------------------------------------------------------------
__global__ void prep_weights(const float* __restrict__ W1, const float* __restrict__ W2,
                             const float* __restrict__ W3, const float* __restrict__ W4)
{
    int idx = blockIdx.x * blockDim.x + threadIdx.x;
    if (idx >= WPK_TOT) return;
    float v;
    if (idx < WPK_W2) {                                  // W1: [128][32]
        int n = idx >> 5, p = idx & 31;
        int kt2 = p >> 4, q = p & 15, mq = q >> 2, j = q & 3;
        v = W1[n * 32 + kt2 * 16 + mq + 4 * j];
    } else if (idx < WPK_W4) {                           // W2 / W3
        int t = idx - WPK_W2;
        const float* W = (t < 16384) ? W2 : W3;
        int r = t & 16383;
        int h = r >> 13, rr = r & 8191;
        int n = rr >> 6, p = rr & 63;
        int kt2 = p >> 4, q = p & 15, mq = q >> 2, j = q & 3;
        v = W[n * 128 + h * 64 + kt2 * 16 + mq + 4 * j];
    } else {                                             // W4: 16 x [100][64]
        int t = idx - WPK_W4;
        int unit = t / 6400, rr = t % 6400;
        int c = unit >> 1, h = unit & 1;
        int n = rr / 64, p = rr % 64;
        int kt2 = p >> 4, q = p & 15, mq = q >> 2, j = q & 3;
        v = W4[(size_t)(c * 100 + n) * 128 + h * 64 + kt2 * 16 + mq + 4 * j];
    }
    g_wpk[idx] = __uint_as_float(tf32_rna(v));
}

// ---------------------------------------------------------------------------
// stage one packed unit (nrows x ROWFL floats) into a weight buffer
template<int ROWFL>
__device__ __forceinline__ void stage_unit(float* dst, const float* src, int nrows) {
    constexpr int CH = ROWFL / 4;
    for (int i = threadIdx.x; i < nrows * CH; i += THREADS) {
        int row = i / CH, j = i - row * CH;
        cp16(dst + row * SW + j * 4, src + row * ROWFL + j * 4);
    }
}

// MMA over one 64-col half: A interleaved (LDS.64), W packed (LDS.128)
// Thread m's float4 at word offset m*4 supplies, per kt2 group:
//   wb.x = W[n][16kt2+m], wb.y = W[n][16kt2+m+4]  (kt even)
//   wb.z = W[n][16kt2+m+8], wb.w = W[n][16kt2+m+12] (kt odd)
template<int NT, int KT2>
__device__ __forceinline__ void mma_tiles(const float* As, const float* Ws, float* C) {
    const int lane = threadIdx.x & 31;
    const int g = lane >> 2, m = lane & 3;
    const float* Ag0 = As + g * SA + m * 2;
    const float* Ag8 = As + (g + 8) * SA + m * 2;
    const float* Wg  = Ws + g * SW + m * 4;
    #pragma unroll
    for (int kt2 = 0; kt2 < KT2; kt2++) {
        float2 ae0 = *(const float2*)(Ag0 + kt2 * 16);       // kt even: rows g
        float2 ae8 = *(const float2*)(Ag8 + kt2 * 16);
        float2 ao0 = *(const float2*)(Ag0 + kt2 * 16 + 8);   // kt odd
        float2 ao8 = *(const float2*)(Ag8 + kt2 * 16 + 8);
        #pragma unroll
        for (int nt = 0; nt < NT; nt++) {
            float4 wb = *(const float4*)(Wg + nt * 8 * SW + kt2 * 16);
            mma8(C + nt * 4, F2U(ae0.x), F2U(ae8.x), F2U(ae0.y), F2U(ae8.y),
                 F2U(wb.x), F2U(wb.y));
            mma8(C + nt * 4, F2U(ao0.x), F2U(ao8.x), F2U(ao0.y), F2U(ao8.y),
                 F2U(wb.z), F2U(wb.w));
        }
    }
}

// relu(C + bias) -> interleaved A tile (own warp rows only), tf32-rounded
__device__ __forceinline__ void relu_store(const float* C, const float* bs,
                                           float* A, int R0) {
    const int lane = threadIdx.x & 31;
    const int g = lane >> 2, m = lane & 3;
    const int c0b = 2 * m, c1b = 2 * m + 1;
    const int P0 = ((c0b & 3) << 1) + (c0b >> 2);
    const int P1 = ((c1b & 3) << 1) + (c1b >> 2);
    #pragma unroll
    for (int nt = 0; nt < 16; nt++) {
        const int c0 = nt * 8 + c0b, c1 = nt * 8 + c1b;
        const float b0 = bs[c0], b1 = bs[c1];
        A[(R0 + g) * SA + nt * 8 + P0]     = __uint_as_float(tf32_rna(fmaxf(C[nt*4+0] + b0, 0.f)));
        A[(R0 + g) * SA + nt * 8 + P1]     = __uint_as_float(tf32_rna(fmaxf(C[nt*4+1] + b1, 0.f)));
        A[(R0 + g + 8) * SA + nt * 8 + P0] = __uint_as_float(tf32_rna(fmaxf(C[nt*4+2] + b0, 0.f)));
        A[(R0 + g + 8) * SA + nt * 8 + P1] = __uint_as_float(tf32_rna(fmaxf(C[nt*4+3] + b1, 0.f)));
    }
}

__device__ __forceinline__ void p_store(const float* C, float* P, int R0) {
    const int lane = threadIdx.x & 31;
    const int g = lane >> 2, m = lane & 3;
    #pragma unroll
    for (int nt = 0; nt < 13; nt++) {
        const int c0 = nt * 8 + 2 * m, c1 = c0 + 1;
        P[(R0 + g) * SP + c0]     = C[nt*4+0];
        P[(R0 + g) * SP + c1]     = C[nt*4+1];
        P[(R0 + g + 8) * SP + c0] = C[nt*4+2];
        P[(R0 + g + 8) * SP + c1] = C[nt*4+3];
    }
}

// ---------------------------------------------------------------------------
__global__ __launch_bounds__(THREADS, 1)
void rqs_mma_kernel(const float* __restrict__ x,
                    const float* __restrict__ b1, const float* __restrict__ b2,
                    const float* __restrict__ b3, const float* __restrict__ b4,
                    float* __restrict__ out, int B)
{
    extern __shared__ float sm[];
    float* A   = sm + A_F;
    float* WBa = sm + WB0_F;
    float* WBb = sm + WB1_F;
    float* P   = sm + P_F;
    float* XTR = sm + XTR_F;
    float* B1S = sm + B1_F;
    float* B2S = sm + B2_F;
    float* B3S = sm + B3_F;
    float* B4S = sm + B4_F;

    const int tid = threadIdx.x;
    const int R0  = (tid >> 5) * 16;
    const long row0 = (long)blockIdx.x * 128;

    // ---- G0: W1 -> WBa, XTR, biases ----
    stage_unit<32>(WBa, g_wpk + WPK_W1, 128);
    for (int i = tid; i < 1024; i += THREADS) {          // x trans
        int row = i >> 3, j = i & 7;
        if (row0 + row < B)
            cp16(XTR + row * SX + j * 4, x + (row0 + row) * 64 + 32 + j * 4);
    }
    for (int i = tid; i < 32; i += THREADS) {
        cp16(B1S + i * 4, b1 + i * 4);
        cp16(B2S + i * 4, b2 + i * 4);
        cp16(B3S + i * 4, b3 + i * 4);
    }
    for (int i = tid; i < 200; i += THREADS) cp16(B4S + i * 4, b4 + i * 4);
    cp_commit();                                         // G0
    stage_unit<64>(WBb, g_wpk + WPK_W2, 128); cp_commit();        // G1: W2h0

    // ---- x_masked: LDG -> tf32 round -> scatter into interleaved A ----
    for (int i = tid; i < 1024; i += THREADS) {
        int row = i >> 3, j = i & 7;
        float4 v = make_float4(0.f, 0.f, 0.f, 0.f);
        if (row0 + row < B) v = *(const float4*)(x + (row0 + row) * 64 + j * 4);
        float* Ar = A + row * SA;
        Ar[apos(j*4+0)] = __uint_as_float(tf32_rna(v.x));
        Ar[apos(j*4+1)] = __uint_as_float(tf32_rna(v.y));
        Ar[apos(j*4+2)] = __uint_as_float(tf32_rna(v.z));
        Ar[apos(j*4+3)] = __uint_as_float(tf32_rna(v.w));
    }

    cp_wait<1>(); __syncthreads();                       // W1 + XTR + biases landed

    float C64[64];

    // ---- Layer 1 (K=32) ----
    #pragma unroll
    for (int i = 0; i < 64; i++) C64[i] = 0.f;
    mma_tiles<16, 2>(A + R0 * SA, WBa, C64);
    relu_store(C64, B1S, A, R0);                         // h1
    __syncthreads();
    stage_unit<64>(WBa, g_wpk + WPK_W2 + 8192, 128); cp_commit();  // W2h1
    cp_wait<1>(); __syncthreads();                       // W2h0 ready

    // ---- Layer 2 ----
    #pragma unroll
    for (int i = 0; i < 64; i++) C64[i] = 0.f;
    mma_tiles<16, 4>(A + R0 * SA, WBb, C64);
    __syncthreads();
    stage_unit<64>(WBb, g_wpk + WPK_W3, 128); cp_commit();         // W3h0
    cp_wait<1>(); __syncthreads();                       // W2h1 ready
    mma_tiles<16, 4>(A + R0 * SA + 64, WBa, C64);
    relu_store(C64, B2S, A, R0);                         // h2
    __syncthreads();
    stage_unit<64>(WBa, g_wpk + WPK_W3 + 8192, 128); cp_commit();  // W3h1
    cp_wait<1>(); __syncthreads();                       // W3h0 ready

    // ---- Layer 3 ----
    #pragma unroll
    for (int i = 0; i < 64; i++) C64[i] = 0.f;
    mma_tiles<16, 4>(A + R0 * SA, WBb, C64);
    __syncthreads();
    stage_unit<64>(WBb, g_wpk + WPK_W4, 100); cp_commit();         // W4 c0 h0
    cp_wait<1>(); __syncthreads();                       // W3h1 ready
    mma_tiles<16, 4>(A + R0 * SA + 64, WBa, C64);
    relu_store(C64, B3S, A, R0);                         // h3
    __syncthreads();

    // ---- Layer 4: 8 chunks of 4 spline dims ----
    const float MINB = 1e-4f;
    const float FREE = 10.f - 8.f * 1e-4f;
    const int trow = tid >> 1;
    float ldsum = 0.f;

    for (int c = 0; c < 8; c++) {
        stage_unit<64>(WBa, g_wpk + WPK_W4 + (c * 2 + 1) * 6400, 100); cp_commit(); // c h1
        cp_wait<1>(); __syncthreads();                   // c h0 ready in WBb

        float C52[52];
        #pragma unroll
        for (int i = 0; i < 52; i++) C52[i] = 0.f;
        mma_tiles<13, 4>(A + R0 * SA, WBb, C52);
        __syncthreads();                                 // done reading WBb
        if (c < 7) {
            stage_unit<64>(WBb, g_wpk + WPK_W4 + (c + 1) * 2 * 6400, 100); cp_commit();
            cp_wait<1>();
        } else {
            cp_wait<0>();
        }
        __syncthreads();                                 // c h1 ready in WBa
        mma_tiles<13, 4>(A + R0 * SA + 64, WBa, C52);
        p_store(C52, P, R0);
        __syncthreads();

        // ---------------- spline epilogue: 2 (row,dim) tasks/thread --------
        #pragma unroll
        for (int j = 0; j < 2; j++) {
            const int q = 2 * (tid & 1) + j;
            const int t = c * 4 + q;

            float acc[25];
            #pragma unroll
            for (int p = 0; p < 25; p++)
                acc[p] = P[trow * SP + q * 25 + p] + B4S[c * 100 + q * 25 + p];

            float m = acc[0];
            #pragma unroll
            for (int i = 1; i < 8; i++) m = fmaxf(m, acc[i]);
            float wdt[8]; float Sw = 0.f;
            #pragma unroll
            for (int i = 0; i < 8; i++) { wdt[i] = __expf(acc[i] - m); Sw += wdt[i]; }
            float mh = acc[8];
            #pragma unroll
            for (int i = 9; i < 16; i++) mh = fmaxf(mh, acc[i]);
            float hgt[8]; float Sh = 0.f;
            #pragma unroll
            for (int i = 0; i < 8; i++) { hgt[i] = __expf(acc[8 + i] - mh); Sh += hgt[i]; }
            const float fw = FREE / Sw, fh = FREE / Sh;
            #pragma unroll
            for (int i = 0; i < 8; i++) {
                wdt[i] = MINB + wdt[i] * fw;
                hgt[i] = MINB + hgt[i] * fh;
            }

            const float xt = XTR[trow * SX + t];
            const float xc = fminf(fmaxf(xt, -5.f), 5.f);
            const bool inside = (xt >= -5.f) && (xt <= 5.f);

            int idx = 0; float cum = -5.f, xk = -5.f, wk = wdt[0];
            #pragma unroll
            for (int i = 0; i < 7; i++) {
                cum += wdt[i];
                if (xc >= cum) { idx = i + 1; xk = cum; wk = wdt[i + 1]; }
            }
            float cumh = -5.f, yk = -5.f, hk = hgt[0];
            #pragma unroll
            for (int i = 0; i < 7; i++) {
                cumh += hgt[i];
                if (idx > i) { yk = cumh; hk = hgt[i + 1]; }
            }
            float sA = acc[16], sB = acc[17];
            #pragma unroll
            for (int i = 1; i < 8; i++)
                if (idx >= i) { sA = acc[16 + i]; sB = acc[17 + i]; }
            const float dk  = 1e-4f + softplus_f(sA);
            const float dk1 = 1e-4f + softplus_f(sB);

            const float rwk  = 1.f / wk;
            const float xi   = (xc - xk) * rwk;
            const float om   = 1.f - xi;
            const float sk   = hk * rwk;
            const float xiom = xi * om;
            const float den  = sk + (dk1 + dk - 2.f * sk) * xiom;
            const float rden = 1.f / den;
            const float num  = sk * xi * xi + dk * xiom;
            const float y_in = yk + hk * num * rden;
            const float num2 = dk1 * xi * xi + 2.f * sk * xiom + dk * om * om;
            const float ld_in = __logf(sk * sk * num2 * rden * rden);

            XTR[trow * SX + t] = inside ? y_in : xt;
            ldsum += inside ? ld_in : 0.f;
        }
    }

    // ---- logdet: pair-reduce ----
    ldsum += __shfl_xor_sync(0xFFFFFFFFu, ldsum, 1);
    if ((tid & 1) == 0 && row0 + trow < B)
        out[(size_t)B * 64 + row0 + trow] = ldsum;

    __syncthreads();

    // ---- flush y ----
    for (int i = tid; i < 2048; i += THREADS) {
        int rr = i >> 4, c4 = i & 15;
        if (row0 + rr >= B) continue;
        float4 v;
        if (c4 < 8) v = *(const float4*)(x + (row0 + rr) * 64 + c4 * 4);
        else        v = *(const float4*)(XTR + rr * SX + (c4 - 8) * 4);
        *(float4*)(out + (row0 + rr) * 64 + c4 * 4) = v;
    }
}

// ---------------------------------------------------------------------------
extern "C" void kernel_launch(void* const* d_in, const int* in_sizes, int n_in,
                              void* d_out, int out_size)
{
    const float* x  = (const float*)d_in[0];
    const float* W1 = (const float*)d_in[1];
    const float* b1 = (const float*)d_in[2];
    const float* W2 = (const float*)d_in[3];
    const float* b2 = (const float*)d_in[4];
    const float* W3 = (const float*)d_in[5];
    const float* b3 = (const float*)d_in[6];
    const float* W4 = (const float*)d_in[7];
    const float* b4 = (const float*)d_in[8];
    float* out = (float*)d_out;

    const int B = in_sizes[0] / 64;

    prep_weights<<<(WPK_TOT + 255) / 256, 256>>>(W1, W2, W3, W4);

    cudaFuncSetAttribute(rqs_mma_kernel,
                         cudaFuncAttributeMaxDynamicSharedMemorySize, SMEM_BYTES);
    const int grid = (B + 127) / 128;
    rqs_mma_kernel<<<grid, THREADS, SMEM_BYTES>>>(x, b1, b2, b3, b4, out, B);
}